// round 9
// baseline (speedup 1.0000x reference)
#include <cuda_runtime.h>

#define KCODES 256
#define DIM 32
#define TPB 128
#define NBLOCKS 456      // 3 CTAs/SM on 152 SMs -> single wave

__global__ void vq_zero_counts(float* counts) {
    counts[threadIdx.x] = 0.0f;
}

typedef unsigned long long ull;

__device__ __forceinline__ ull pack2(float lo, float hi) {
    ull r;
    asm("mov.b64 %0, {%1, %2};" : "=l"(r) : "f"(lo), "f"(hi));
    return r;
}
__device__ __forceinline__ void unpack2(ull v, float& lo, float& hi) {
    asm("mov.b64 {%0, %1}, %2;" : "=f"(lo), "=f"(hi) : "l"(v));
}

// One block: 8 dims (D..D+7) of codes k (addrA) and k+1 (addrB).
// Codebook rows are stored duplicated: 16B at jj holds (c_{2jj},c_{2jj},c_{2jj+1},c_{2jj+1}).
// All LDS and all c-operands stay INSIDE the asm block (no marshal MOVs);
// only read-only xp inputs and tied accumulators cross the boundary.
// FMA order per accumulator: strictly ascending d -> bit-exact sequential chain.
#define FMA2BLK(a01, a23, b01, b23, xlo, xhi, D, addrA, addrB)                  \
    asm volatile(                                                               \
        "{\n\t"                                                                 \
        ".reg .b64 ca0,ca1,ca2,ca3,ca4,ca5,ca6,ca7;\n\t"                        \
        ".reg .b64 cb0,cb1,cb2,cb3,cb4,cb5,cb6,cb7;\n\t"                        \
        "ld.shared.v2.u64 {ca0,ca1}, [%20+%22];\n\t"                            \
        "ld.shared.v2.u64 {ca2,ca3}, [%20+%23];\n\t"                            \
        "ld.shared.v2.u64 {ca4,ca5}, [%20+%24];\n\t"                            \
        "ld.shared.v2.u64 {ca6,ca7}, [%20+%25];\n\t"                            \
        "ld.shared.v2.u64 {cb0,cb1}, [%21+%22];\n\t"                            \
        "ld.shared.v2.u64 {cb2,cb3}, [%21+%23];\n\t"                            \
        "ld.shared.v2.u64 {cb4,cb5}, [%21+%24];\n\t"                            \
        "ld.shared.v2.u64 {cb6,cb7}, [%21+%25];\n\t"                            \
        "fma.rn.f32x2 %0, %4,  ca0, %0;\n\t"                                    \
        "fma.rn.f32x2 %1, %12, ca0, %1;\n\t"                                    \
        "fma.rn.f32x2 %2, %4,  cb0, %2;\n\t"                                    \
        "fma.rn.f32x2 %3, %12, cb0, %3;\n\t"                                    \
        "fma.rn.f32x2 %0, %5,  ca1, %0;\n\t"                                    \
        "fma.rn.f32x2 %1, %13, ca1, %1;\n\t"                                    \
        "fma.rn.f32x2 %2, %5,  cb1, %2;\n\t"                                    \
        "fma.rn.f32x2 %3, %13, cb1, %3;\n\t"                                    \
        "fma.rn.f32x2 %0, %6,  ca2, %0;\n\t"                                    \
        "fma.rn.f32x2 %1, %14, ca2, %1;\n\t"                                    \
        "fma.rn.f32x2 %2, %6,  cb2, %2;\n\t"                                    \
        "fma.rn.f32x2 %3, %14, cb2, %3;\n\t"                                    \
        "fma.rn.f32x2 %0, %7,  ca3, %0;\n\t"                                    \
        "fma.rn.f32x2 %1, %15, ca3, %1;\n\t"                                    \
        "fma.rn.f32x2 %2, %7,  cb3, %2;\n\t"                                    \
        "fma.rn.f32x2 %3, %15, cb3, %3;\n\t"                                    \
        "fma.rn.f32x2 %0, %8,  ca4, %0;\n\t"                                    \
        "fma.rn.f32x2 %1, %16, ca4, %1;\n\t"                                    \
        "fma.rn.f32x2 %2, %8,  cb4, %2;\n\t"                                    \
        "fma.rn.f32x2 %3, %16, cb4, %3;\n\t"                                    \
        "fma.rn.f32x2 %0, %9,  ca5, %0;\n\t"                                    \
        "fma.rn.f32x2 %1, %17, ca5, %1;\n\t"                                    \
        "fma.rn.f32x2 %2, %9,  cb5, %2;\n\t"                                    \
        "fma.rn.f32x2 %3, %17, cb5, %3;\n\t"                                    \
        "fma.rn.f32x2 %0, %10, ca6, %0;\n\t"                                    \
        "fma.rn.f32x2 %1, %18, ca6, %1;\n\t"                                    \
        "fma.rn.f32x2 %2, %10, cb6, %2;\n\t"                                    \
        "fma.rn.f32x2 %3, %18, cb6, %3;\n\t"                                    \
        "fma.rn.f32x2 %0, %11, ca7, %0;\n\t"                                    \
        "fma.rn.f32x2 %1, %19, ca7, %1;\n\t"                                    \
        "fma.rn.f32x2 %2, %11, cb7, %2;\n\t"                                    \
        "fma.rn.f32x2 %3, %19, cb7, %3;\n\t"                                    \
        "}"                                                                     \
        : "+l"(a01), "+l"(a23), "+l"(b01), "+l"(b23)                            \
        : "l"(xlo[(D)+0]), "l"(xlo[(D)+1]), "l"(xlo[(D)+2]), "l"(xlo[(D)+3]),   \
          "l"(xlo[(D)+4]), "l"(xlo[(D)+5]), "l"(xlo[(D)+6]), "l"(xlo[(D)+7]),   \
          "l"(xhi[(D)+0]), "l"(xhi[(D)+1]), "l"(xhi[(D)+2]), "l"(xhi[(D)+3]),   \
          "l"(xhi[(D)+4]), "l"(xhi[(D)+5]), "l"(xhi[(D)+6]), "l"(xhi[(D)+7]),   \
          "r"(addrA), "r"(addrB),                                               \
          "n"((D)*8), "n"((D)*8+16), "n"((D)*8+32), "n"((D)*8+48));

__global__ __launch_bounds__(TPB, 3) void vq_main(
    const float* __restrict__ x,
    const float* __restrict__ cb,
    float* __restrict__ out_rot,
    float* __restrict__ out_idx,
    float* __restrict__ out_counts,
    int nQuads)
{
    // Duplicated codebook: row k = (c0,c0,c1,c1,...,c31,c31), 256B/row, 64 KB.
    __shared__ __align__(16) float cbd[KCODES * DIM * 2];
    __shared__ float c2_s[KCODES];
    __shared__ float hist[KCODES];

    const int tid = threadIdx.x;

    // --- Stage duplicated codebook; c2 exact (rounded squares, sequential sum) ---
    for (int k = tid; k < KCODES; k += TPB) {
        const float4* src = reinterpret_cast<const float4*>(cb + k * DIM);
        float4* dst = reinterpret_cast<float4*>(cbd + k * (DIM * 2));
        float row[DIM];
        #pragma unroll
        for (int j = 0; j < 8; j++) {
            float4 v = src[j];
            row[4*j+0] = v.x; row[4*j+1] = v.y; row[4*j+2] = v.z; row[4*j+3] = v.w;
        }
        #pragma unroll
        for (int jj = 0; jj < 16; jj++) {
            float4 w;
            w.x = row[2*jj];     w.y = row[2*jj];
            w.z = row[2*jj + 1]; w.w = row[2*jj + 1];
            dst[jj] = w;
        }
        float s = 0.0f;
        #pragma unroll
        for (int d = 0; d < DIM; d++)
            s = __fadd_rn(s, __fmul_rn(row[d], row[d]));
        c2_s[k] = s;
        hist[k] = 0.0f;
    }
    __syncthreads();

    // 32-bit shared address of cbd for asm LDS.
    unsigned int cbd_addr;
    {
        unsigned long long tmp;
        asm("cvta.to.shared.u64 %0, %1;" : "=l"(tmp) : "l"(cbd));
        cbd_addr = (unsigned int)tmp;
    }

    const int qs = (int)(((long long)blockIdx.x * nQuads) / NBLOCKS);
    const int qe = (int)(((long long)(blockIdx.x + 1) * nQuads) / NBLOCKS);

    for (int q = qs + tid; q < qe; q += TPB) {
        const float* xb = x + (long long)q * (4 * DIM);

        // Load 4 tokens; compute x2 scalar-sequential (reference order); pack pairs.
        ull xp01[DIM], xp23[DIM];
        float x2v[4];
        {
            float s0=0.f, s1=0.f, s2=0.f, s3=0.f;
            #pragma unroll
            for (int j = 0; j < 8; j++) {
                float4 a = reinterpret_cast<const float4*>(xb        )[j];
                float4 b = reinterpret_cast<const float4*>(xb +   DIM)[j];
                float4 c = reinterpret_cast<const float4*>(xb + 2*DIM)[j];
                float4 d = reinterpret_cast<const float4*>(xb + 3*DIM)[j];
                xp01[4*j+0] = pack2(a.x, b.x); xp23[4*j+0] = pack2(c.x, d.x);
                xp01[4*j+1] = pack2(a.y, b.y); xp23[4*j+1] = pack2(c.y, d.y);
                xp01[4*j+2] = pack2(a.z, b.z); xp23[4*j+2] = pack2(c.z, d.z);
                xp01[4*j+3] = pack2(a.w, b.w); xp23[4*j+3] = pack2(c.w, d.w);
                s0=__fadd_rn(s0,__fmul_rn(a.x,a.x)); s0=__fadd_rn(s0,__fmul_rn(a.y,a.y));
                s0=__fadd_rn(s0,__fmul_rn(a.z,a.z)); s0=__fadd_rn(s0,__fmul_rn(a.w,a.w));
                s1=__fadd_rn(s1,__fmul_rn(b.x,b.x)); s1=__fadd_rn(s1,__fmul_rn(b.y,b.y));
                s1=__fadd_rn(s1,__fmul_rn(b.z,b.z)); s1=__fadd_rn(s1,__fmul_rn(b.w,b.w));
                s2=__fadd_rn(s2,__fmul_rn(c.x,c.x)); s2=__fadd_rn(s2,__fmul_rn(c.y,c.y));
                s2=__fadd_rn(s2,__fmul_rn(c.z,c.z)); s2=__fadd_rn(s2,__fmul_rn(c.w,c.w));
                s3=__fadd_rn(s3,__fmul_rn(d.x,d.x)); s3=__fadd_rn(s3,__fmul_rn(d.y,d.y));
                s3=__fadd_rn(s3,__fmul_rn(d.z,d.z)); s3=__fadd_rn(s3,__fmul_rn(d.w,d.w));
            }
            x2v[0]=s0; x2v[1]=s1; x2v[2]=s2; x2v[3]=s3;
        }

        float best[4] = {3.4e38f, 3.4e38f, 3.4e38f, 3.4e38f};
        int   bi[4]   = {0, 0, 0, 0};

        unsigned int addrA = cbd_addr;            // code k   row (256 B each)
        unsigned int addrB = cbd_addr + 256;      // code k+1 row

        // --- Argmin scan: 2 codes/iter × 4 tokens, all FMA/LDS inside asm ---
        #pragma unroll 1
        for (int k = 0; k < KCODES; k += 2) {
            ull a01 = 0ull, a23 = 0ull;   // dots vs code k   (tokens 0,1 / 2,3)
            ull b01 = 0ull, b23 = 0ull;   // dots vs code k+1

            FMA2BLK(a01, a23, b01, b23, xp01, xp23,  0, addrA, addrB)
            FMA2BLK(a01, a23, b01, b23, xp01, xp23,  8, addrA, addrB)
            FMA2BLK(a01, a23, b01, b23, xp01, xp23, 16, addrA, addrB)
            FMA2BLK(a01, a23, b01, b23, xp01, xp23, 24, addrA, addrB)

            addrA += 512; addrB += 512;

            // d2 = fl(fl(x2 - 2*dot) + c2); strict <, ascending k = first-index ties
            float d00, d01, d02, d03, d10, d11, d12, d13;
            unpack2(a01, d00, d01); unpack2(a23, d02, d03);
            unpack2(b01, d10, d11); unpack2(b23, d12, d13);
            const float c2a = c2_s[k], c2b = c2_s[k + 1];
            float va0 = __fadd_rn(__fadd_rn(x2v[0], __fmul_rn(-2.0f, d00)), c2a);
            float va1 = __fadd_rn(__fadd_rn(x2v[1], __fmul_rn(-2.0f, d01)), c2a);
            float va2 = __fadd_rn(__fadd_rn(x2v[2], __fmul_rn(-2.0f, d02)), c2a);
            float va3 = __fadd_rn(__fadd_rn(x2v[3], __fmul_rn(-2.0f, d03)), c2a);
            float vb0 = __fadd_rn(__fadd_rn(x2v[0], __fmul_rn(-2.0f, d10)), c2b);
            float vb1 = __fadd_rn(__fadd_rn(x2v[1], __fmul_rn(-2.0f, d11)), c2b);
            float vb2 = __fadd_rn(__fadd_rn(x2v[2], __fmul_rn(-2.0f, d12)), c2b);
            float vb3 = __fadd_rn(__fadd_rn(x2v[3], __fmul_rn(-2.0f, d13)), c2b);
            bool u;
            u = va0 < best[0]; best[0] = u ? va0 : best[0]; bi[0] = u ? k : bi[0];
            u = va1 < best[1]; best[1] = u ? va1 : best[1]; bi[1] = u ? k : bi[1];
            u = va2 < best[2]; best[2] = u ? va2 : best[2]; bi[2] = u ? k : bi[2];
            u = va3 < best[3]; best[3] = u ? va3 : best[3]; bi[3] = u ? k : bi[3];
            u = vb0 < best[0]; best[0] = u ? vb0 : best[0]; bi[0] = u ? k+1 : bi[0];
            u = vb1 < best[1]; best[1] = u ? vb1 : best[1]; bi[1] = u ? k+1 : bi[1];
            u = vb2 < best[2]; best[2] = u ? vb2 : best[2]; bi[2] = u ? k+1 : bi[2];
            u = vb3 < best[3]; best[3] = u ? vb3 : best[3]; bi[3] = u ? k+1 : bi[3];
        }

        // --- Per-token epilogue: histogram + rotation-trick output ---
        #pragma unroll
        for (int t = 0; t < 4; t++) {
            const int code = bi[t];
            atomicAdd(&hist[code], 1.0f);

            float xr[DIM];
            #pragma unroll
            for (int d = 0; d < DIM; d++) {
                float lo, hi;
                if (t < 2) { unpack2(xp01[d], lo, hi); }
                else       { unpack2(xp23[d], lo, hi); }
                xr[d] = (t & 1) ? hi : lo;
            }

            float qv[DIM];
            const float4* qrow = reinterpret_cast<const float4*>(cb + code * DIM);
            #pragma unroll
            for (int j = 0; j < 8; j++) {
                float4 v = __ldg(qrow + j);
                qv[4*j+0] = v.x; qv[4*j+1] = v.y; qv[4*j+2] = v.z; qv[4*j+3] = v.w;
            }

            float q2 = 0.f, dotq = 0.f;
            #pragma unroll
            for (int d = 0; d < DIM; d++) {
                q2   = __fmaf_rn(qv[d], qv[d], q2);
                dotq = __fmaf_rn(xr[d], qv[d], dotq);
            }
            const float eps = 1e-6f;
            const float x2t = x2v[t];
            float inx = 1.0f / fmaxf(sqrtf(x2t), eps);
            float inq = 1.0f / fmaxf(sqrtf(q2),  eps);
            float u2  = x2t * inx * inx;
            float qh2 = q2  * inq * inq;
            float uq  = dotq * inx * inq;
            float w2  = u2 + qh2 + 2.0f * uq;
            float iw  = 1.0f / fmaxf(sqrtf(w2), eps);
            float ew_un = x2t * inx + dotq * inq;
            float ew  = ew_un * iw;
            float eu  = x2t * inx;
            float a   = -2.0f * ew * iw;
            float s1  = 1.0f + a * inx;
            float s2  = (a + 2.0f * eu) * inq;

            float4* rp = reinterpret_cast<float4*>(out_rot + ((long long)q * 4 + t) * DIM);
            #pragma unroll
            for (int j = 0; j < 8; j++) {
                float4 v;
                v.x = xr[4*j+0] * s1 + qv[4*j+0] * s2;
                v.y = xr[4*j+1] * s1 + qv[4*j+1] * s2;
                v.z = xr[4*j+2] * s1 + qv[4*j+2] * s2;
                v.w = xr[4*j+3] * s1 + qv[4*j+3] * s2;
                rp[j] = v;
            }
            out_idx[(long long)q * 4 + t] = (float)code;
        }
    }

    // --- Flush block-local histogram ---
    __syncthreads();
    for (int k = tid; k < KCODES; k += TPB)
        atomicAdd(&out_counts[k], hist[k]);
}

extern "C" void kernel_launch(void* const* d_in, const int* in_sizes, int n_in,
                              void* d_out, int out_size) {
    const float* x  = (const float*)d_in[0];
    const float* cb = (const float*)d_in[1];
    float* out = (float*)d_out;

    const int N = in_sizes[0] / DIM;            // 524288
    const int nQuads = N / 4;                   // 131072
    float* rot    = out;
    float* idx    = out + (size_t)N * DIM;
    float* counts = idx + N;

    vq_zero_counts<<<1, KCODES>>>(counts);
    vq_main<<<NBLOCKS, TPB>>>(x, cb, rot, idx, counts, nQuads);
}

// round 11
// speedup vs baseline: 2.0930x; 2.0930x over previous
#include <cuda_runtime.h>

#define KCODES 256
#define DIM 32
#define TPB 128
#define NTILES 4096          // 524288 / 128 tokens per CTA
#define STRIDE 36            // padded row stride in words (conflict-free frags)
#define CANDCAP 6

typedef unsigned u32;

__global__ void vq_zero_counts(float* counts) {
    counts[threadIdx.x] = 0.0f;
}

__device__ __forceinline__ u32 to_tf32(float f) {
    u32 u;
    asm("cvt.rna.tf32.f32 %0, %1;" : "=r"(u) : "f"(f));
    return u;
}

__device__ __forceinline__ void mma_tf32(float d[4], const u32 a[4], u32 b0, u32 b1) {
    asm volatile(
        "mma.sync.aligned.m16n8k8.row.col.f32.tf32.tf32.f32 "
        "{%0,%1,%2,%3},{%4,%5,%6,%7},{%8,%9},{%0,%1,%2,%3};"
        : "+f"(d[0]), "+f"(d[1]), "+f"(d[2]), "+f"(d[3])
        : "r"(a[0]), "r"(a[1]), "r"(a[2]), "r"(a[3]), "r"(b0), "r"(b1));
}

__global__ __launch_bounds__(TPB) void vq_tc(
    const float* __restrict__ x,
    const float* __restrict__ cb,
    float* __restrict__ out_rot,
    float* __restrict__ out_idx,
    float* __restrict__ out_counts)
{
    extern __shared__ __align__(16) u32 smem_dyn[];
    u32* As = smem_dyn;                      // 128 * 36 tf32 words
    u32* Bs = smem_dyn + 128 * STRIDE;       // 256 * 36 tf32 words

    __shared__ float c2_s[KCODES];
    __shared__ float hist[KCODES];
    __shared__ float best_s[TPB];
    __shared__ float thr_s[TPB];
    __shared__ int   cand_cnt[TPB];
    __shared__ int   cand[TPB * CANDCAP];

    const int tid  = threadIdx.x;
    const int lane = tid & 31;
    const int wid  = tid >> 5;
    const int gid  = lane >> 2;
    const int tig  = lane & 3;
    const int m0   = wid * 32;

    // ---- Stage A: token tid (exact x in regs; tf32 copy to smem); exact x2 ----
    const long long tok0 = (long long)blockIdx.x * TPB;
    float xr[DIM];
    float x2;
    {
        const float4* xp = reinterpret_cast<const float4*>(x + (tok0 + tid) * DIM);
        #pragma unroll
        for (int j = 0; j < 8; j++) {
            float4 v = xp[j];
            xr[4*j+0] = v.x; xr[4*j+1] = v.y; xr[4*j+2] = v.z; xr[4*j+3] = v.w;
        }
        float s = 0.0f;
        #pragma unroll
        for (int d = 0; d < DIM; d++)
            s = __fadd_rn(s, __fmul_rn(xr[d], xr[d]));
        x2 = s;
        #pragma unroll
        for (int d = 0; d < DIM; d++)
            As[tid * STRIDE + d] = to_tf32(xr[d]);
    }

    // ---- Stage B: codebook (2 rows/thread), exact c2, zero hist ----
    #pragma unroll
    for (int rr = 0; rr < 2; rr++) {
        const int r = tid + rr * TPB;
        const float4* src = reinterpret_cast<const float4*>(cb + r * DIM);
        float row[DIM];
        #pragma unroll
        for (int j = 0; j < 8; j++) {
            float4 v = __ldg(src + j);
            row[4*j+0] = v.x; row[4*j+1] = v.y; row[4*j+2] = v.z; row[4*j+3] = v.w;
        }
        float s = 0.0f;
        #pragma unroll
        for (int d = 0; d < DIM; d++)
            s = __fadd_rn(s, __fmul_rn(row[d], row[d]));
        c2_s[r] = s;
        hist[r] = 0.0f;
        #pragma unroll
        for (int d = 0; d < DIM; d++)
            Bs[r * STRIDE + d] = to_tf32(row[d]);
    }
    __syncthreads();

    // ---- Load A fragments (2 m-tiles x 4 k-steps x 4 regs = 32 regs) ----
    u32 afr[2][4][4];
    #pragma unroll
    for (int mt = 0; mt < 2; mt++) {
        const int r0 = m0 + mt * 16 + gid;
        #pragma unroll
        for (int ks = 0; ks < 4; ks++) {
            const int k0 = ks * 8 + tig;
            afr[mt][ks][0] = As[ r0      * STRIDE + k0];
            afr[mt][ks][1] = As[(r0 + 8) * STRIDE + k0];
            afr[mt][ks][2] = As[ r0      * STRIDE + k0 + 4];
            afr[mt][ks][3] = As[(r0 + 8) * STRIDE + k0 + 4];
        }
    }

    // ---- Pass 1: min of s = c2 - 2*dot per token-row slice ----
    float mn[2][2] = {{3.4e38f, 3.4e38f}, {3.4e38f, 3.4e38f}};  // [mtile][lo/hi]
    #pragma unroll 1
    for (int c = 0; c < 32; c++) {
        u32 bfr[4][2];
        #pragma unroll
        for (int ks = 0; ks < 4; ks++) {
            const int nrow = c * 8 + gid;
            bfr[ks][0] = Bs[nrow * STRIDE + ks * 8 + tig];
            bfr[ks][1] = Bs[nrow * STRIDE + ks * 8 + tig + 4];
        }
        const float c2a = c2_s[c * 8 + tig * 2];
        const float c2b = c2_s[c * 8 + tig * 2 + 1];
        #pragma unroll
        for (int mt = 0; mt < 2; mt++) {
            float d[4] = {0.f, 0.f, 0.f, 0.f};
            #pragma unroll
            for (int ks = 0; ks < 4; ks++)
                mma_tf32(d, afr[mt][ks], bfr[ks][0], bfr[ks][1]);
            float s0 = __fmaf_rn(-2.0f, d[0], c2a);
            float s1 = __fmaf_rn(-2.0f, d[1], c2b);
            float s2 = __fmaf_rn(-2.0f, d[2], c2a);
            float s3 = __fmaf_rn(-2.0f, d[3], c2b);
            mn[mt][0] = fminf(mn[mt][0], fminf(s0, s1));
            mn[mt][1] = fminf(mn[mt][1], fminf(s2, s3));
        }
    }
    // quad reduce (lanes sharing gid)
    #pragma unroll
    for (int mt = 0; mt < 2; mt++) {
        #pragma unroll
        for (int h = 0; h < 2; h++) {
            float v = mn[mt][h];
            v = fminf(v, __shfl_xor_sync(0xFFFFFFFFu, v, 1));
            v = fminf(v, __shfl_xor_sync(0xFFFFFFFFu, v, 2));
            mn[mt][h] = v;
        }
    }
    if (tig == 0) {
        best_s[m0 + gid]      = mn[0][0];
        best_s[m0 + gid + 8]  = mn[0][1];
        best_s[m0 + gid + 16] = mn[1][0];
        best_s[m0 + gid + 24] = mn[1][1];
    }
    __syncthreads();

    // ---- Threshold: rigorous tf32 error bound (2x margin) ----
    {
        float twotau = __fmaf_rn(sqrtf(x2), 1e-4f, 4e-5f);
        thr_s[tid] = best_s[tid] + twotau;
        cand_cnt[tid] = 0;
    }
    __syncthreads();

    // ---- Pass 2: identical MMAs; flag candidates ----
    const float thrA_lo = thr_s[m0 + gid];
    const float thrA_hi = thr_s[m0 + gid + 8];
    const float thrB_lo = thr_s[m0 + gid + 16];
    const float thrB_hi = thr_s[m0 + gid + 24];
    #pragma unroll 1
    for (int c = 0; c < 32; c++) {
        u32 bfr[4][2];
        #pragma unroll
        for (int ks = 0; ks < 4; ks++) {
            const int nrow = c * 8 + gid;
            bfr[ks][0] = Bs[nrow * STRIDE + ks * 8 + tig];
            bfr[ks][1] = Bs[nrow * STRIDE + ks * 8 + tig + 4];
        }
        const int col0 = c * 8 + tig * 2;
        const float c2a = c2_s[col0];
        const float c2b = c2_s[col0 + 1];
        #pragma unroll
        for (int mt = 0; mt < 2; mt++) {
            float d[4] = {0.f, 0.f, 0.f, 0.f};
            #pragma unroll
            for (int ks = 0; ks < 4; ks++)
                mma_tf32(d, afr[mt][ks], bfr[ks][0], bfr[ks][1]);
            const float tlo = mt ? thrB_lo : thrA_lo;
            const float thi = mt ? thrB_hi : thrA_hi;
            const int rlo = m0 + mt * 16 + gid;
            const int rhi = rlo + 8;
            float s0 = __fmaf_rn(-2.0f, d[0], c2a);
            float s1 = __fmaf_rn(-2.0f, d[1], c2b);
            float s2 = __fmaf_rn(-2.0f, d[2], c2a);
            float s3 = __fmaf_rn(-2.0f, d[3], c2b);
            if (s0 <= tlo) { int sl = atomicAdd(&cand_cnt[rlo], 1); if (sl < CANDCAP) cand[rlo * CANDCAP + sl] = col0; }
            if (s1 <= tlo) { int sl = atomicAdd(&cand_cnt[rlo], 1); if (sl < CANDCAP) cand[rlo * CANDCAP + sl] = col0 + 1; }
            if (s2 <= thi) { int sl = atomicAdd(&cand_cnt[rhi], 1); if (sl < CANDCAP) cand[rhi * CANDCAP + sl] = col0; }
            if (s3 <= thi) { int sl = atomicAdd(&cand_cnt[rhi], 1); if (sl < CANDCAP) cand[rhi * CANDCAP + sl] = col0 + 1; }
        }
    }
    __syncthreads();

    // ---- Exact recheck for token tid (R1 bit-exact d2; first-index ties) ----
    int bi = 0;
    {
        const int cnt = cand_cnt[tid];
        float bestE = 3.4e38f;
        if (cnt <= CANDCAP) {
            for (int i = 0; i < cnt; i++) {
                const int k = cand[tid * CANDCAP + i];
                const float4* qr = reinterpret_cast<const float4*>(cb + k * DIM);
                float dotx = 0.0f;
                #pragma unroll
                for (int jj = 0; jj < 8; jj++) {
                    float4 q4 = __ldg(qr + jj);
                    dotx = __fmaf_rn(xr[4*jj+0], q4.x, dotx);
                    dotx = __fmaf_rn(xr[4*jj+1], q4.y, dotx);
                    dotx = __fmaf_rn(xr[4*jj+2], q4.z, dotx);
                    dotx = __fmaf_rn(xr[4*jj+3], q4.w, dotx);
                }
                float d2 = __fadd_rn(__fadd_rn(x2, __fmul_rn(-2.0f, dotx)), c2_s[k]);
                if (d2 < bestE || (d2 == bestE && k < bi)) { bestE = d2; bi = k; }
            }
        } else {
            // overflow: deterministic full exact scan, ascending k, strict <
            for (int k = 0; k < KCODES; k++) {
                const float4* qr = reinterpret_cast<const float4*>(cb + k * DIM);
                float dotx = 0.0f;
                #pragma unroll
                for (int jj = 0; jj < 8; jj++) {
                    float4 q4 = __ldg(qr + jj);
                    dotx = __fmaf_rn(xr[4*jj+0], q4.x, dotx);
                    dotx = __fmaf_rn(xr[4*jj+1], q4.y, dotx);
                    dotx = __fmaf_rn(xr[4*jj+2], q4.z, dotx);
                    dotx = __fmaf_rn(xr[4*jj+3], q4.w, dotx);
                }
                float d2 = __fadd_rn(__fadd_rn(x2, __fmul_rn(-2.0f, dotx)), c2_s[k]);
                if (d2 < bestE) { bestE = d2; bi = k; }
            }
        }
    }

    // ---- Epilogue: histogram + rotation-trick output ----
    atomicAdd(&hist[bi], 1.0f);
    {
        float qv[DIM];
        const float4* qrow = reinterpret_cast<const float4*>(cb + bi * DIM);
        #pragma unroll
        for (int j = 0; j < 8; j++) {
            float4 v = __ldg(qrow + j);
            qv[4*j+0] = v.x; qv[4*j+1] = v.y; qv[4*j+2] = v.z; qv[4*j+3] = v.w;
        }
        float q2 = 0.f, dotq = 0.f;
        #pragma unroll
        for (int d = 0; d < DIM; d++) {
            q2   = __fmaf_rn(qv[d], qv[d], q2);
            dotq = __fmaf_rn(xr[d], qv[d], dotq);
        }
        const float eps = 1e-6f;
        float inx = 1.0f / fmaxf(sqrtf(x2), eps);
        float inq = 1.0f / fmaxf(sqrtf(q2), eps);
        float u2  = x2 * inx * inx;
        float qh2 = q2 * inq * inq;
        float uq  = dotq * inx * inq;
        float w2  = u2 + qh2 + 2.0f * uq;
        float iw  = 1.0f / fmaxf(sqrtf(w2), eps);
        float ew  = (x2 * inx + dotq * inq) * iw;
        float eu  = x2 * inx;
        float a   = -2.0f * ew * iw;
        float s1  = 1.0f + a * inx;
        float s2  = (a + 2.0f * eu) * inq;

        float4* rp = reinterpret_cast<float4*>(out_rot + (tok0 + tid) * DIM);
        #pragma unroll
        for (int j = 0; j < 8; j++) {
            float4 v;
            v.x = xr[4*j+0] * s1 + qv[4*j+0] * s2;
            v.y = xr[4*j+1] * s1 + qv[4*j+1] * s2;
            v.z = xr[4*j+2] * s1 + qv[4*j+2] * s2;
            v.w = xr[4*j+3] * s1 + qv[4*j+3] * s2;
            rp[j] = v;
        }
        out_idx[tok0 + tid] = (float)bi;
    }

    // ---- Flush histogram ----
    __syncthreads();
    #pragma unroll
    for (int rr = 0; rr < 2; rr++)
        atomicAdd(&out_counts[tid + rr * TPB], hist[tid + rr * TPB]);
}

extern "C" void kernel_launch(void* const* d_in, const int* in_sizes, int n_in,
                              void* d_out, int out_size) {
    const float* x  = (const float*)d_in[0];
    const float* cb = (const float*)d_in[1];
    float* out = (float*)d_out;

    const int N = in_sizes[0] / DIM;            // 524288
    float* rot    = out;
    float* idx    = out + (size_t)N * DIM;
    float* counts = idx + N;

    const int dyn = (128 + 256) * STRIDE * 4;   // 55296 B
    cudaFuncSetAttribute(vq_tc, cudaFuncAttributeMaxDynamicSharedMemorySize, dyn);
    vq_zero_counts<<<1, KCODES>>>(counts);
    vq_tc<<<NTILES, TPB, dyn>>>(x, cb, rot, idx, counts);
}